// round 1
// baseline (speedup 1.0000x reference)
#include <cuda_runtime.h>
#include <math.h>

#define T    2048
#define NF   6142     // 3T-2
#define L4   4096
#define M0C  4094     // 2T-2
#define BATCH 64

// ---------------- device scratch (no allocs allowed) ----------------
__device__ float2 g_tw[2048];        // e^{-2pi i k/4096}, k<2048
__device__ float2 g_phaseU[2048];    // e^{i pi (2 j m0 + j^2)/N}
__device__ float2 g_psi[2048];       // e^{2pi i (2(T-1)(m0+m') + m'^2)/N}
__device__ float2 g_W[4096];         // DIF-ordered FFT of chirp w_k = e^{-i pi k^2/N}
__device__ float  g_q[4 * 2048];     // f_rev, g, fp_rev, gp
__device__ float2 g_H[4 * 2048];     // Htilde per filter
__device__ float  g_A[9 * BATCH * T];  // A   flattened, layout [c][b][t]
__device__ float  g_B[9 * BATCH * T];  // A^-1 flattened, layout [c][b][t]

__device__ __forceinline__ float2 cmul(float2 a, float2 b) {
    return make_float2(fmaf(a.x, b.x, -a.y * b.y), fmaf(a.x, b.y, a.y * b.x));
}

// ---------------- shared-memory FFT (block-cooperative) ----------------
// DIF forward: natural in -> bit-reversed out.  Twiddle table is for L=4096;
// index k*(2048/half) == k*(4096/size) works for any power-of-2 L <= 4096.
__device__ void fft_dif(float2* x, int L, const float2* tw) {
    int tid = threadIdx.x, nt = blockDim.x;
    for (int half = L >> 1; half >= 1; half >>= 1) {
        int tmul = 2048 / half;
        for (int q = tid; q < (L >> 1); q += nt) {
            int k = q & (half - 1);
            int ia = 2 * q - k;
            int ib = ia + half;
            float2 a = x[ia], b = x[ib];
            float2 w = tw[k * tmul];
            x[ia] = make_float2(a.x + b.x, a.y + b.y);
            float2 d = make_float2(a.x - b.x, a.y - b.y);
            x[ib] = cmul(d, w);
        }
        __syncthreads();
    }
}

// DIT inverse (no 1/L scaling): bit-reversed in -> natural out, e^{+2pi i} twiddles.
__device__ void fft_dit_inv(float2* x, int L, const float2* tw) {
    int tid = threadIdx.x, nt = blockDim.x;
    for (int half = 1; half <= (L >> 1); half <<= 1) {
        int tmul = 2048 / half;
        for (int q = tid; q < (L >> 1); q += nt) {
            int k = q & (half - 1);
            int ia = 2 * q - k;
            int ib = ia + half;
            float2 a = x[ia];
            float2 w = tw[k * tmul];
            float2 b = cmul(x[ib], make_float2(w.x, -w.y));
            x[ia] = make_float2(a.x + b.x, a.y + b.y);
            x[ib] = make_float2(a.x - b.x, a.y - b.y);
        }
        __syncthreads();
    }
}

// ---------------- precompute kernels ----------------
__global__ void k_tables() {
    int i = blockIdx.x * blockDim.x + threadIdx.x;
    if (i >= 2048) return;
    float s, c;
    sincospif((float)i / 2048.0f, &s, &c);
    g_tw[i] = make_float2(c, -s);

    long long j = i;
    long long idxU = (2LL * j * M0C + j * j) % (2LL * NF);
    sincospif((float)idxU / (float)NF, &s, &c);
    g_phaseU[i] = make_float2(c, s);

    long long e2 = (2LL * (T - 1) * (M0C + j) + j * j) % NF;
    sincospif(2.0f * (float)e2 / (float)NF, &s, &c);
    g_psi[i] = make_float2(c, s);
}

__global__ void k_W() {
    __shared__ float2 buf[4096];
    int tid = threadIdx.x;
    for (int n = tid; n < 4096; n += blockDim.x) {
        if (n == 2048) { buf[n] = make_float2(0.f, 0.f); continue; }
        long long k = (n < 2048) ? n : (4096 - n);
        long long idx = (k * k) % (2LL * NF);
        float s, c;
        sincospif((float)idx / (float)NF, &s, &c);
        buf[n] = make_float2(c, -s);
    }
    __syncthreads();
    fft_dif(buf, 4096, g_tw);
    for (int n = tid; n < 4096; n += blockDim.x) g_W[n] = buf[n];
}

struct FnnW { const float *w1, *b1, *w2, *b2; };

__global__ void k_fnn(FnnW wf, FnnW wg, FnnW wfp, FnnW wgp) {
    int i = blockIdx.x * blockDim.x + threadIdx.x;
    if (i >= 4 * 2048) return;
    int q = i >> 11, p = i & 2047;
    FnnW W = (q == 0) ? wf : (q == 1) ? wg : (q == 2) ? wfp : wgp;
    float x = (q == 0 || q == 2) ? (float)(T - 1 - p) : (float)p;  // f, fp reversed
    float z = W.b2[0];
#pragma unroll
    for (int h = 0; h < 5; h++)
        z += W.w2[h] * tanhf(W.w1[h] * x + W.b1[h]);
    g_q[i] = z * expf(-5.0f * x);
}

// Htilde[q][j] = sum_p q_t[p] * e^{-2pi i ((j+T-1)(p+T-1) mod N)/N}  — warp per j,
// complex phase recurrence (one cmul per term), exact integer phase start.
__global__ void k_H() {
    int gw = (blockIdx.x * blockDim.x + threadIdx.x) >> 5;
    int lane = threadIdx.x & 31;
    if (gw >= 4 * 2048) return;
    int q = gw >> 11, j = gw & 2047;
    long long base = j + (T - 1);
    long long idx0 = (base * (long long)(lane + T - 1)) % NF;
    float s, c;
    sincospif(2.0f * (float)idx0 / (float)NF, &s, &c);
    float2 ph = make_float2(c, -s);
    long long idxs = (base * 32LL) % NF;
    sincospif(2.0f * (float)idxs / (float)NF, &s, &c);
    float2 st = make_float2(c, -s);
    float2 acc = make_float2(0.f, 0.f);
    const float* qq = g_q + q * 2048;
#pragma unroll 8
    for (int it = 0; it < 64; it++) {
        float v = qq[lane + 32 * it];
        acc.x = fmaf(v, ph.x, acc.x);
        acc.y = fmaf(v, ph.y, acc.y);
        ph = cmul(ph, st);
    }
    for (int off = 16; off; off >>= 1) {
        acc.x += __shfl_down_sync(0xffffffffu, acc.x, off);
        acc.y += __shfl_down_sync(0xffffffffu, acc.y, off);
    }
    if (lane == 0) g_H[q * 2048 + j] = acc;
}

// ---------------- rotation prefix scan ----------------
__device__ __forceinline__ void rod(float vx, float vy, float vz, float* M) {
    float t2 = vx * vx + vy * vy + vz * vz;
    float th = sqrtf(t2);
    float a, bb;
    if (t2 < 1e-8f) {
        a = 1.0f - t2 * (1.0f / 6.0f);
        bb = 0.5f - t2 * (1.0f / 24.0f);
    } else {
        a = sinf(th) / th;
        float sh = sinf(0.5f * th);
        bb = 2.0f * sh * sh / t2;   // (1-cos)/t2, cancellation-free
    }
    float ct = 1.0f - bb * t2;      // cos(theta)
    M[0] = ct + bb * vx * vx; M[1] = bb * vx * vy - a * vz; M[2] = bb * vx * vz + a * vy;
    M[3] = bb * vy * vx + a * vz; M[4] = ct + bb * vy * vy; M[5] = bb * vy * vz - a * vx;
    M[6] = bb * vz * vx - a * vy; M[7] = bb * vz * vy + a * vx; M[8] = ct + bb * vz * vz;
}

__device__ __forceinline__ void mm3(const float* A, const float* B, float* C) {
    float t[9];
#pragma unroll
    for (int i = 0; i < 3; i++)
#pragma unroll
        for (int j = 0; j < 3; j++)
            t[3 * i + j] = A[3 * i] * B[j] + A[3 * i + 1] * B[3 + j] + A[3 * i + 2] * B[6 + j];
#pragma unroll
    for (int k = 0; k < 9; k++) C[k] = t[k];
}

__device__ __forceinline__ void inv3(const float* A, float* B) {
    float c00 = A[4] * A[8] - A[5] * A[7];
    float c01 = A[5] * A[6] - A[3] * A[8];
    float c02 = A[3] * A[7] - A[4] * A[6];
    float id = 1.0f / (A[0] * c00 + A[1] * c01 + A[2] * c02);
    B[0] = c00 * id; B[1] = (A[2] * A[7] - A[1] * A[8]) * id; B[2] = (A[1] * A[5] - A[2] * A[4]) * id;
    B[3] = c01 * id; B[4] = (A[0] * A[8] - A[2] * A[6]) * id; B[5] = (A[2] * A[3] - A[0] * A[5]) * id;
    B[6] = c02 * id; B[7] = (A[1] * A[6] - A[0] * A[7]) * id; B[8] = (A[0] * A[4] - A[1] * A[3]) * id;
}

// one block per batch; 256 threads x 8-element chunks; Hillis-Steele matrix scan
__global__ void k_scan(const float* __restrict__ xd,
                       const float* __restrict__ A1, const float* __restrict__ A2) {
    __shared__ float sP[256][9];
    __shared__ float sv[6];
    int b = blockIdx.x, tid = threadIdx.x;
    if (tid == 0) {
        sv[0] = A1[7] - A1[5]; sv[1] = A1[2] - A1[6]; sv[2] = A1[3] - A1[1];
        sv[3] = A2[7] - A2[5]; sv[4] = A2[2] - A2[6]; sv[5] = A2[3] - A2[1];
    }
    __syncthreads();
    float v1x = sv[0], v1y = sv[1], v1z = sv[2], v2x = sv[3], v2y = sv[4], v2z = sv[5];

    float P[9] = {1, 0, 0, 0, 1, 0, 0, 0, 1};
    int t0 = tid * 8;
    for (int tt = 0; tt < 8; tt++) {
        int t = t0 + tt;
        if (t == 0) continue;  // M_0 := I
        float z1 = xd[(b * T + t) * 2], z2 = xd[(b * T + t) * 2 + 1];
        float M[9];
        rod(z1 * v1x + z2 * v2x, z1 * v1y + z2 * v2y, z1 * v1z + z2 * v2z, M);
        mm3(P, M, P);
    }
    float mine[9];
#pragma unroll
    for (int k = 0; k < 9; k++) { mine[k] = P[k]; sP[tid][k] = P[k]; }
    __syncthreads();
    for (int off = 1; off < 256; off <<= 1) {
        float Lm[9];
        bool act = (tid >= off);
        if (act)
#pragma unroll
            for (int k = 0; k < 9; k++) Lm[k] = sP[tid - off][k];
        __syncthreads();
        if (act) {
            mm3(Lm, mine, mine);
#pragma unroll
            for (int k = 0; k < 9; k++) sP[tid][k] = mine[k];
        }
        __syncthreads();
    }
    float X[9] = {1, 0, 0, 0, 1, 0, 0, 0, 1};
    if (tid > 0)
#pragma unroll
        for (int k = 0; k < 9; k++) X[k] = sP[tid - 1][k];

    for (int tt = 0; tt < 8; tt++) {
        int t = t0 + tt;
        if (t != 0) {
            float z1 = xd[(b * T + t) * 2], z2 = xd[(b * T + t) * 2 + 1];
            float M[9];
            rod(z1 * v1x + z2 * v2x, z1 * v1y + z2 * v2y, z1 * v1z + z2 * v2z, M);
            mm3(X, M, X);
        }
        float Bi[9];
        inv3(X, Bi);
#pragma unroll
        for (int c = 0; c < 9; c++) {
            g_A[(c * BATCH + b) * T + t] = X[c];
            g_B[(c * BATCH + b) * T + t] = Bi[c];
        }
    }
}

// ---------------- main kernel: one block per (b, c) ----------------
extern __shared__ float2 sm[];
__global__ void k_main(float* __restrict__ out) {
    float2* s_tw = sm;           // 2048
    float2* s_Z = sm + 2048;     // 2048  natural-order FFT of packed signal
    float2* s_c1 = sm + 4096;    // 2048  conv AA / BA
    float2* s_P = sm + 6144;     // 2048  accumulator
    float2* s_buf = sm + 8192;   // 4096  FFT workspace

    int b = blockIdx.x / 9, c = blockIdx.x % 9;
    int tid = threadIdx.x, nt = blockDim.x;

    for (int k = tid; k < 2048; k += nt) s_tw[k] = g_tw[k];
    const float* Ar = g_A + (c * BATCH + b) * T;
    const float* Ai = g_B + (c * BATCH + b) * T;
    for (int t = tid; t < 2048; t += nt)
        s_buf[t] = make_float2(Ai[t], Ar[t]);   // z = Xir + i*Xr
    __syncthreads();

    fft_dif(s_buf, 2048, s_tw);
    for (int j = tid; j < 2048; j += nt) s_Z[j] = s_buf[__brev((unsigned)j) >> 21];
    __syncthreads();

    const float sc = 1.0f / ((float)L4 * (float)NF);
    for (int s = 0; s < 4; s++) {
        for (int j = tid; j < 2048; j += nt) {
            float2 Zj = s_Z[j];
            float2 Zm = s_Z[(2048 - j) & 2047];
            float2 X;
            if (s == 0 || s == 2)   // Xir = (Z + conj(Zm))/2
                X = make_float2(0.5f * (Zj.x + Zm.x), 0.5f * (Zj.y - Zm.y));
            else                    // Xr = (Z - conj(Zm))/(2i)
                X = make_float2(0.5f * (Zj.y + Zm.y), 0.5f * (Zm.x - Zj.x));
            float2 u = cmul(cmul(X, g_H[s * 2048 + j]), g_phaseU[j]);
            s_buf[j] = u;
            s_buf[j + 2048] = make_float2(0.f, 0.f);
        }
        __syncthreads();
        fft_dif(s_buf, 4096, s_tw);
        for (int k = tid; k < 4096; k += nt) s_buf[k] = cmul(s_buf[k], g_W[k]);
        __syncthreads();
        fft_dit_inv(s_buf, 4096, s_tw);
        for (int m = tid; m < 2048; m += nt) {
            float2 v = make_float2(s_buf[m].x * sc, s_buf[m].y * sc);
            if (s == 0 || s == 2) {
                s_c1[m] = v;
            } else if (s == 1) {
                s_P[m] = cmul(s_c1[m], v);
            } else {
                float2 p = cmul(s_c1[m], v);
                s_P[m].x += p.x; s_P[m].y += p.y;
            }
        }
        __syncthreads();
    }
    for (int m = tid; m < 2048; m += nt) {
        float2 p = cmul(s_P[m], g_psi[m]);
        out[(b * T + m) * 9 + c] = p.x;
    }
}

// ---------------- launch ----------------
extern "C" void kernel_launch(void* const* d_in, const int* in_sizes, int n_in,
                              void* d_out, int out_size) {
    const float* xd = (const float*)d_in[0];
    const float* A1 = (const float*)d_in[1];
    const float* A2 = (const float*)d_in[2];
    FnnW wf  = {(const float*)d_in[3],  (const float*)d_in[4],  (const float*)d_in[5],  (const float*)d_in[6]};
    FnnW wg  = {(const float*)d_in[7],  (const float*)d_in[8],  (const float*)d_in[9],  (const float*)d_in[10]};
    FnnW wfp = {(const float*)d_in[11], (const float*)d_in[12], (const float*)d_in[13], (const float*)d_in[14]};
    FnnW wgp = {(const float*)d_in[15], (const float*)d_in[16], (const float*)d_in[17], (const float*)d_in[18]};
    float* out = (float*)d_out;

    cudaFuncSetAttribute(k_main, cudaFuncAttributeMaxDynamicSharedMemorySize, 98304);

    k_tables<<<8, 256>>>();
    k_fnn<<<32, 256>>>(wf, wg, wfp, wgp);
    k_W<<<1, 512>>>();
    k_H<<<1024, 256>>>();
    k_scan<<<BATCH, 256>>>(xd, A1, A2);
    k_main<<<BATCH * 9, 512, 98304>>>(out);
}

// round 2
// speedup vs baseline: 1.5440x; 1.5440x over previous
#include <cuda_runtime.h>
#include <math.h>

#define T    2048
#define NF   6142     // 3T-2
#define M0C  4094     // 2T-2
#define BATCH 64

// ---------------- device scratch (no allocs allowed) ----------------
__device__ float2 g_tw[2048];        // e^{-2pi i k/4096}, k<2048
__device__ float2 g_phaseU[2048];    // e^{i pi (2 j m0 + j^2)/N}
__device__ float2 g_psi[2048];       // e^{2pi i (2(T-1)(m0+m') + m'^2)/N}
__device__ float2 g_W[4096];         // radix4-DIF-ordered FFT of chirp w_k = e^{-i pi k^2/N}
__device__ float  g_q[4 * 2048];     // f_rev, g, fp_rev, gp
__device__ float2 g_UH[4 * 2048];    // Htilde * phaseU per filter
__device__ float  g_A[9 * BATCH * T];  // A    flattened [c][b][t]
__device__ float  g_B[9 * BATCH * T];  // A^-1 flattened [c][b][t]

__device__ __forceinline__ float2 cmul(float2 a, float2 b) {
    return make_float2(fmaf(a.x, b.x, -a.y * b.y), fmaf(a.x, b.y, a.y * b.x));
}
__device__ __forceinline__ float2 cmulc(float2 a, float2 b) {  // a * conj(b)
    return make_float2(fmaf(a.x, b.x, a.y * b.y), fmaf(a.y, b.x, -a.x * b.y));
}

// ---------------- radix-2 DIF (for the 2048 FFT only) ----------------
__device__ void fft_dif_r2(float2* x, int L, const float2* tw) {
    int tid = threadIdx.x, nt = blockDim.x;
    for (int half = L >> 1; half >= 1; half >>= 1) {
        int tmul = 2048 / half;
        for (int q = tid; q < (L >> 1); q += nt) {
            int k = q & (half - 1);
            int ia = 2 * q - k;
            int ib = ia + half;
            float2 a = x[ia], b = x[ib];
            float2 w = tw[k * tmul];
            x[ia] = make_float2(a.x + b.x, a.y + b.y);
            float2 d = make_float2(a.x - b.x, a.y - b.y);
            x[ib] = cmul(d, w);
        }
        __syncthreads();
    }
}

// ---------------- radix-4 stages (L = 4096 fixed) ----------------
// DIF forward stages: size_hi down to size_lo (powers of 4 apart).
__device__ void r4_dif(float2* x, const float2* tw, int size_hi, int size_lo) {
    for (int size = size_hi; size >= size_lo; size >>= 2) {
        int q = size >> 2;
        int tmul = 4096 / size;
        for (int v = threadIdx.x; v < 1024; v += blockDim.x) {
            int k = v & (q - 1);
            int i0 = ((v & ~(q - 1)) << 2) + k;
            float2 a = x[i0], b = x[i0 + q], c = x[i0 + 2 * q], d = x[i0 + 3 * q];
            float2 apc = make_float2(a.x + c.x, a.y + c.y);
            float2 amc = make_float2(a.x - c.x, a.y - c.y);
            float2 bpd = make_float2(b.x + d.x, b.y + d.y);
            float2 bmd = make_float2(b.x - d.x, b.y - d.y);
            float2 w1 = tw[k * tmul], w2 = tw[2 * k * tmul];
            float2 w3 = cmul(w1, w2);
            x[i0] = make_float2(apc.x + bpd.x, apc.y + bpd.y);
            float2 y1 = make_float2(amc.x + bmd.y, amc.y - bmd.x);  // (a-c) - i(b-d)
            float2 y2 = make_float2(apc.x - bpd.x, apc.y - bpd.y);
            float2 y3 = make_float2(amc.x - bmd.y, amc.y + bmd.x);  // (a-c) + i(b-d)
            x[i0 + q]     = cmul(y1, w1);
            x[i0 + 2 * q] = cmul(y2, w2);
            x[i0 + 3 * q] = cmul(y3, w3);
        }
        __syncthreads();
    }
}

// DIT inverse stages: size_lo up to size_hi. Unscaled (x L total over full chain).
__device__ void r4_dit_inv(float2* x, const float2* tw, int size_lo, int size_hi) {
    for (int size = size_lo; size <= size_hi; size <<= 2) {
        int q = size >> 2;
        int tmul = 4096 / size;
        for (int v = threadIdx.x; v < 1024; v += blockDim.x) {
            int k = v & (q - 1);
            int i0 = ((v & ~(q - 1)) << 2) + k;
            float2 w1 = tw[k * tmul], w2 = tw[2 * k * tmul];
            float2 Y0 = x[i0];
            float2 Y1 = cmulc(x[i0 + q], w1);
            float2 Y2 = cmulc(x[i0 + 2 * q], w2);
            float2 Y3 = cmulc(cmulc(x[i0 + 3 * q], w1), w2);
            float2 p0 = make_float2(Y0.x + Y2.x, Y0.y + Y2.y);
            float2 p1 = make_float2(Y0.x - Y2.x, Y0.y - Y2.y);
            float2 s0 = make_float2(Y1.x + Y3.x, Y1.y + Y3.y);
            float2 s1 = make_float2(Y1.x - Y3.x, Y1.y - Y3.y);
            x[i0]         = make_float2(p0.x + s0.x, p0.y + s0.y);
            x[i0 + q]     = make_float2(p1.x - s1.y, p1.y + s1.x);  // + i*s1
            x[i0 + 2 * q] = make_float2(p0.x - s0.x, p0.y - s0.y);
            x[i0 + 3 * q] = make_float2(p1.x + s1.y, p1.y - s1.x);  // - i*s1
        }
        __syncthreads();
    }
}

// ---------------- precompute kernels ----------------
__global__ void k_tables() {
    int i = blockIdx.x * blockDim.x + threadIdx.x;
    if (i >= 2048) return;
    float s, c;
    sincospif((float)i / 2048.0f, &s, &c);
    g_tw[i] = make_float2(c, -s);

    long long j = i;
    long long idxU = (2LL * j * M0C + j * j) % (2LL * NF);
    sincospif((float)idxU / (float)NF, &s, &c);
    g_phaseU[i] = make_float2(c, s);

    long long e2 = (2LL * (T - 1) * (M0C + j) + j * j) % NF;
    sincospif(2.0f * (float)e2 / (float)NF, &s, &c);
    g_psi[i] = make_float2(c, s);
}

__global__ void k_W() {
    __shared__ float2 buf[4096];
    int tid = threadIdx.x;
    for (int n = tid; n < 4096; n += blockDim.x) {
        if (n == 2048) { buf[n] = make_float2(0.f, 0.f); continue; }
        long long k = (n < 2048) ? n : (4096 - n);
        long long idx = (k * k) % (2LL * NF);
        float s, c;
        sincospif((float)idx / (float)NF, &s, &c);
        buf[n] = make_float2(c, -s);
    }
    __syncthreads();
    r4_dif(buf, g_tw, 4096, 4);
    for (int n = tid; n < 4096; n += blockDim.x) g_W[n] = buf[n];
}

struct FnnW { const float *w1, *b1, *w2, *b2; };

__global__ void k_fnn(FnnW wf, FnnW wg, FnnW wfp, FnnW wgp) {
    int i = blockIdx.x * blockDim.x + threadIdx.x;
    if (i >= 4 * 2048) return;
    int q = i >> 11, p = i & 2047;
    FnnW W = (q == 0) ? wf : (q == 1) ? wg : (q == 2) ? wfp : wgp;
    float x = (q == 0 || q == 2) ? (float)(T - 1 - p) : (float)p;  // f, fp reversed
    float z = W.b2[0];
#pragma unroll
    for (int h = 0; h < 5; h++)
        z += W.w2[h] * tanhf(W.w1[h] * x + W.b1[h]);
    g_q[i] = z * expf(-5.0f * x);
}

// UH[q][j] = phaseU[j] * sum_p q_t[p] e^{-2pi i ((j+T-1)(p+T-1) mod N)/N}
__global__ void k_H() {
    int gw = (blockIdx.x * blockDim.x + threadIdx.x) >> 5;
    int lane = threadIdx.x & 31;
    if (gw >= 4 * 2048) return;
    int q = gw >> 11, j = gw & 2047;
    long long base = j + (T - 1);
    long long idx0 = (base * (long long)(lane + T - 1)) % NF;
    float s, c;
    sincospif(2.0f * (float)idx0 / (float)NF, &s, &c);
    float2 ph = make_float2(c, -s);
    long long idxs = (base * 32LL) % NF;
    sincospif(2.0f * (float)idxs / (float)NF, &s, &c);
    float2 st = make_float2(c, -s);
    float2 acc = make_float2(0.f, 0.f);
    const float* qq = g_q + q * 2048;
#pragma unroll 8
    for (int it = 0; it < 64; it++) {
        float v = qq[lane + 32 * it];
        acc.x = fmaf(v, ph.x, acc.x);
        acc.y = fmaf(v, ph.y, acc.y);
        ph = cmul(ph, st);
    }
    for (int off = 16; off; off >>= 1) {
        acc.x += __shfl_down_sync(0xffffffffu, acc.x, off);
        acc.y += __shfl_down_sync(0xffffffffu, acc.y, off);
    }
    if (lane == 0) g_UH[q * 2048 + j] = cmul(acc, g_phaseU[j]);
}

// ---------------- rotation prefix scan ----------------
__device__ __forceinline__ void rod(float vx, float vy, float vz, float* M) {
    float t2 = vx * vx + vy * vy + vz * vz;
    float th = sqrtf(t2);
    float a, bb;
    if (t2 < 1e-8f) {
        a = 1.0f - t2 * (1.0f / 6.0f);
        bb = 0.5f - t2 * (1.0f / 24.0f);
    } else {
        a = sinf(th) / th;
        float sh = sinf(0.5f * th);
        bb = 2.0f * sh * sh / t2;
    }
    float ct = 1.0f - bb * t2;
    M[0] = ct + bb * vx * vx; M[1] = bb * vx * vy - a * vz; M[2] = bb * vx * vz + a * vy;
    M[3] = bb * vy * vx + a * vz; M[4] = ct + bb * vy * vy; M[5] = bb * vy * vz - a * vx;
    M[6] = bb * vz * vx - a * vy; M[7] = bb * vz * vy + a * vx; M[8] = ct + bb * vz * vz;
}

__device__ __forceinline__ void mm3(const float* A, const float* B, float* C) {
    float t[9];
#pragma unroll
    for (int i = 0; i < 3; i++)
#pragma unroll
        for (int j = 0; j < 3; j++)
            t[3 * i + j] = A[3 * i] * B[j] + A[3 * i + 1] * B[3 + j] + A[3 * i + 2] * B[6 + j];
#pragma unroll
    for (int k = 0; k < 9; k++) C[k] = t[k];
}

__device__ __forceinline__ void inv3(const float* A, float* B) {
    float c00 = A[4] * A[8] - A[5] * A[7];
    float c01 = A[5] * A[6] - A[3] * A[8];
    float c02 = A[3] * A[7] - A[4] * A[6];
    float id = 1.0f / (A[0] * c00 + A[1] * c01 + A[2] * c02);
    B[0] = c00 * id; B[1] = (A[2] * A[7] - A[1] * A[8]) * id; B[2] = (A[1] * A[5] - A[2] * A[4]) * id;
    B[3] = c01 * id; B[4] = (A[0] * A[8] - A[2] * A[6]) * id; B[5] = (A[2] * A[3] - A[0] * A[5]) * id;
    B[6] = c02 * id; B[7] = (A[1] * A[6] - A[0] * A[7]) * id; B[8] = (A[0] * A[4] - A[1] * A[3]) * id;
}

__global__ void k_scan(const float* __restrict__ xd,
                       const float* __restrict__ A1, const float* __restrict__ A2) {
    __shared__ float sP[256][9];
    __shared__ float sv[6];
    int b = blockIdx.x, tid = threadIdx.x;
    if (tid == 0) {
        sv[0] = A1[7] - A1[5]; sv[1] = A1[2] - A1[6]; sv[2] = A1[3] - A1[1];
        sv[3] = A2[7] - A2[5]; sv[4] = A2[2] - A2[6]; sv[5] = A2[3] - A2[1];
    }
    __syncthreads();
    float v1x = sv[0], v1y = sv[1], v1z = sv[2], v2x = sv[3], v2y = sv[4], v2z = sv[5];

    float P[9] = {1, 0, 0, 0, 1, 0, 0, 0, 1};
    int t0 = tid * 8;
    for (int tt = 0; tt < 8; tt++) {
        int t = t0 + tt;
        if (t == 0) continue;
        float z1 = xd[(b * T + t) * 2], z2 = xd[(b * T + t) * 2 + 1];
        float M[9];
        rod(z1 * v1x + z2 * v2x, z1 * v1y + z2 * v2y, z1 * v1z + z2 * v2z, M);
        mm3(P, M, P);
    }
    float mine[9];
#pragma unroll
    for (int k = 0; k < 9; k++) { mine[k] = P[k]; sP[tid][k] = P[k]; }
    __syncthreads();
    for (int off = 1; off < 256; off <<= 1) {
        float Lm[9];
        bool act = (tid >= off);
        if (act)
#pragma unroll
            for (int k = 0; k < 9; k++) Lm[k] = sP[tid - off][k];
        __syncthreads();
        if (act) {
            mm3(Lm, mine, mine);
#pragma unroll
            for (int k = 0; k < 9; k++) sP[tid][k] = mine[k];
        }
        __syncthreads();
    }
    float X[9] = {1, 0, 0, 0, 1, 0, 0, 0, 1};
    if (tid > 0)
#pragma unroll
        for (int k = 0; k < 9; k++) X[k] = sP[tid - 1][k];

    for (int tt = 0; tt < 8; tt++) {
        int t = t0 + tt;
        if (t != 0) {
            float z1 = xd[(b * T + t) * 2], z2 = xd[(b * T + t) * 2 + 1];
            float M[9];
            rod(z1 * v1x + z2 * v2x, z1 * v1y + z2 * v2y, z1 * v1z + z2 * v2z, M);
            mm3(X, M, X);
        }
        float Bi[9];
        inv3(X, Bi);
#pragma unroll
        for (int c = 0; c < 9; c++) {
            g_A[(c * BATCH + b) * T + t] = X[c];
            g_B[(c * BATCH + b) * T + t] = Bi[c];
        }
    }
}

// ---------------- main kernel: one block per (b, c), 512 threads ----------------
extern __shared__ float2 sm[];
__global__ void k_main(float* __restrict__ out) {
    float2* s_tw  = sm;           // 2048 (16KB)
    float2* s_Z   = sm + 2048;    // 2048 (16KB)
    float2* s_buf = sm + 4096;    // 4096 (32KB)

    int b = blockIdx.x / 9, c = blockIdx.x % 9;
    int tid = threadIdx.x, nt = blockDim.x;  // nt == 512

    for (int k = tid; k < 2048; k += nt) s_tw[k] = g_tw[k];
    const float* Ar = g_A + (c * BATCH + b) * T;
    const float* Ai = g_B + (c * BATCH + b) * T;
    for (int t = tid; t < 2048; t += nt)
        s_buf[t] = make_float2(Ai[t], Ar[t]);   // z = Xir + i*Xr
    __syncthreads();

    fft_dif_r2(s_buf, 2048, s_tw);
    for (int j = tid; j < 2048; j += nt) s_Z[j] = s_buf[__brev((unsigned)j) >> 21];
    __syncthreads();

    float2 c1[4], P[4];
    const float sc = 1.0f / (4096.0f * (float)NF);

    for (int s = 0; s < 4; s++) {
        bool useIr = (s == 0 || s == 2);
        const float2* UH = g_UH + s * 2048;

        // --- fused forward stage 1 (size=4096, upper half of u is zero) ---
        for (int v = tid; v < 1024; v += nt) {
            float2 ua, ub;
            {
                int j = v;
                float2 Zj = s_Z[j], Zm = s_Z[(2048 - j) & 2047];
                float2 X = useIr
                    ? make_float2(0.5f * (Zj.x + Zm.x), 0.5f * (Zj.y - Zm.y))
                    : make_float2(0.5f * (Zj.y + Zm.y), 0.5f * (Zm.x - Zj.x));
                ua = cmul(X, UH[j]);
            }
            {
                int j = v + 1024;
                float2 Zj = s_Z[j], Zm = s_Z[2048 - j];
                float2 X = useIr
                    ? make_float2(0.5f * (Zj.x + Zm.x), 0.5f * (Zj.y - Zm.y))
                    : make_float2(0.5f * (Zj.y + Zm.y), 0.5f * (Zm.x - Zj.x));
                ub = cmul(X, UH[j]);
            }
            float2 w1 = s_tw[v], w2 = s_tw[2 * v];
            float2 w3 = cmul(w1, w2);
            s_buf[v] = make_float2(ua.x + ub.x, ua.y + ub.y);
            float2 y1 = make_float2(ua.x + ub.y, ua.y - ub.x);  // a - i b
            float2 y2 = make_float2(ua.x - ub.x, ua.y - ub.y);
            float2 y3 = make_float2(ua.x - ub.y, ua.y + ub.x);  // a + i b
            s_buf[v + 1024] = cmul(y1, w1);
            s_buf[v + 2048] = cmul(y2, w2);
            s_buf[v + 3072] = cmul(y3, w3);
        }
        __syncthreads();

        r4_dif(s_buf, s_tw, 1024, 4);   // remaining 5 forward stages

        // --- fused inverse stage 1 (size=4, twiddles unity) with W multiply ---
        {
            const float4* W4 = (const float4*)g_W;
            float4* B4 = (float4*)s_buf;
            for (int v = tid; v < 1024; v += nt) {
                float4 x01 = B4[2 * v], x23 = B4[2 * v + 1];
                float4 w01 = W4[2 * v], w23 = W4[2 * v + 1];
                float2 Y0 = cmul(make_float2(x01.x, x01.y), make_float2(w01.x, w01.y));
                float2 Y1 = cmul(make_float2(x01.z, x01.w), make_float2(w01.z, w01.w));
                float2 Y2 = cmul(make_float2(x23.x, x23.y), make_float2(w23.x, w23.y));
                float2 Y3 = cmul(make_float2(x23.z, x23.w), make_float2(w23.z, w23.w));
                float2 p0 = make_float2(Y0.x + Y2.x, Y0.y + Y2.y);
                float2 p1 = make_float2(Y0.x - Y2.x, Y0.y - Y2.y);
                float2 s0 = make_float2(Y1.x + Y3.x, Y1.y + Y3.y);
                float2 s1 = make_float2(Y1.x - Y3.x, Y1.y - Y3.y);
                B4[2 * v]     = make_float4(p0.x + s0.x, p0.y + s0.y, p1.x - s1.y, p1.y + s1.x);
                B4[2 * v + 1] = make_float4(p0.x - s0.x, p0.y - s0.y, p1.x + s1.y, p1.y - s1.x);
            }
            __syncthreads();
        }

        r4_dit_inv(s_buf, s_tw, 16, 1024);  // middle 4 inverse stages

        // --- fused last inverse stage (size=4096): only outputs m < 2048, into regs ---
#pragma unroll
        for (int i = 0; i < 2; i++) {
            int v = tid + i * 512;
            float2 w1 = s_tw[v], w2 = s_tw[2 * v];
            float2 Y0 = s_buf[v];
            float2 Y1 = cmulc(s_buf[v + 1024], w1);
            float2 Y2 = cmulc(s_buf[v + 2048], w2);
            float2 Y3 = cmulc(cmulc(s_buf[v + 3072], w1), w2);
            float2 e = make_float2((Y0.x + Y2.x + Y1.x + Y3.x) * sc,
                                   (Y0.y + Y2.y + Y1.y + Y3.y) * sc);      // m = v
            float2 p1 = make_float2(Y0.x - Y2.x, Y0.y - Y2.y);
            float2 s1 = make_float2(Y1.x - Y3.x, Y1.y - Y3.y);
            float2 o = make_float2((p1.x - s1.y) * sc, (p1.y + s1.x) * sc); // m = v+1024
            int r0 = 2 * i, r1 = 2 * i + 1;
            if (s == 0 || s == 2) {
                c1[r0] = e; c1[r1] = o;
            } else if (s == 1) {
                P[r0] = cmul(c1[r0], e); P[r1] = cmul(c1[r1], o);
            } else {
                float2 t1 = cmul(c1[r0], e); P[r0].x += t1.x; P[r0].y += t1.y;
                float2 t2 = cmul(c1[r1], o); P[r1].x += t2.x; P[r1].y += t2.y;
            }
        }
        __syncthreads();  // protect s_buf before next round's stage-1 writes
    }

    int ms[4] = {tid, tid + 1024, tid + 512, tid + 1536};
#pragma unroll
    for (int r = 0; r < 4; r++) {
        float2 psi = g_psi[ms[r]];
        out[(b * T + ms[r]) * 9 + c] = P[r].x * psi.x - P[r].y * psi.y;
    }
}

// ---------------- launch ----------------
extern "C" void kernel_launch(void* const* d_in, const int* in_sizes, int n_in,
                              void* d_out, int out_size) {
    const float* xd = (const float*)d_in[0];
    const float* A1 = (const float*)d_in[1];
    const float* A2 = (const float*)d_in[2];
    FnnW wf  = {(const float*)d_in[3],  (const float*)d_in[4],  (const float*)d_in[5],  (const float*)d_in[6]};
    FnnW wg  = {(const float*)d_in[7],  (const float*)d_in[8],  (const float*)d_in[9],  (const float*)d_in[10]};
    FnnW wfp = {(const float*)d_in[11], (const float*)d_in[12], (const float*)d_in[13], (const float*)d_in[14]};
    FnnW wgp = {(const float*)d_in[15], (const float*)d_in[16], (const float*)d_in[17], (const float*)d_in[18]};
    float* out = (float*)d_out;

    cudaFuncSetAttribute(k_main, cudaFuncAttributeMaxDynamicSharedMemorySize, 65536);

    k_tables<<<8, 256>>>();
    k_fnn<<<32, 256>>>(wf, wg, wfp, wgp);
    k_W<<<1, 512>>>();
    k_H<<<1024, 256>>>();
    k_scan<<<BATCH, 256>>>(xd, A1, A2);
    k_main<<<BATCH * 9, 512, 65536>>>(out);
}

// round 3
// speedup vs baseline: 3.2710x; 2.1185x over previous
#include <cuda_runtime.h>
#include <math.h>

#define T    2048
#define NF   6142     // 3T-2
#define M0C  4094     // 2T-2
#define BATCH 64

// ---------------- device scratch ----------------
__device__ float2 g_tw[2048];        // e^{-2pi i k/4096}
__device__ float2 g_phaseU[2048];
__device__ float2 g_psi[2048];
__device__ float2 g_W[4096];         // digit-ordered FFT of chirp (same transform as k_main fwd)
__device__ float  g_q[4 * 2048];
__device__ float2 g_UH[4 * 2048];    // Htilde * phaseU
__device__ float  g_A[9 * BATCH * T];
__device__ float  g_B[9 * BATCH * T];

__device__ __forceinline__ float2 cmul(float2 a, float2 b) {
    return make_float2(fmaf(a.x, b.x, -a.y * b.y), fmaf(a.x, b.y, a.y * b.x));
}
__device__ __forceinline__ float2 cmulc(float2 a, float2 b) {  // a * conj(b)
    return make_float2(fmaf(a.x, b.x, a.y * b.y), fmaf(a.y, b.x, -a.x * b.y));
}
__device__ __forceinline__ float2 cadd(float2 a, float2 b) { return make_float2(a.x + b.x, a.y + b.y); }
__device__ __forceinline__ float2 csub(float2 a, float2 b) { return make_float2(a.x - b.x, a.y - b.y); }
__device__ __forceinline__ int PAD(int e) { return e + (e >> 3) + (e >> 6); }

#define RC8 0.70710678118654752440f

// 8-point DFT, natural in/out, omega = e^{-2pi i/8}
__device__ __forceinline__ void fwd8(float2* a) {
    float2 F0=cadd(a[0],a[4]), F1=csub(a[0],a[4]);
    float2 G0=cadd(a[2],a[6]), G1=csub(a[2],a[6]);
    float2 H0=cadd(a[1],a[5]), H1=csub(a[1],a[5]);
    float2 K0=cadd(a[3],a[7]), K1=csub(a[3],a[7]);
    float2 E0=cadd(F0,G0), E2=csub(F0,G0);
    float2 E1=make_float2(F1.x+G1.y, F1.y-G1.x);   // F1 - i G1
    float2 E3=make_float2(F1.x-G1.y, F1.y+G1.x);   // F1 + i G1
    float2 O0=cadd(H0,K0), O2=csub(H0,K0);
    float2 O1=make_float2(H1.x+K1.y, H1.y-K1.x);
    float2 O3=make_float2(H1.x-K1.y, H1.y+K1.x);
    float2 t1=make_float2(RC8*(O1.x+O1.y),  RC8*(O1.y-O1.x));   // w8^1 * O1
    float2 t2=make_float2(O2.y, -O2.x);                          // -i O2
    float2 t3=make_float2(RC8*(O3.y-O3.x), -RC8*(O3.x+O3.y));   // w8^3 * O3
    a[0]=cadd(E0,O0); a[4]=csub(E0,O0);
    a[1]=cadd(E1,t1); a[5]=csub(E1,t1);
    a[2]=cadd(E2,t2); a[6]=csub(E2,t2);
    a[3]=cadd(E3,t3); a[7]=csub(E3,t3);
}

// inverse 8-point DFT (omega = e^{+2pi i/8}), unscaled
__device__ __forceinline__ void inv8(float2* a) {
    float2 F0=cadd(a[0],a[4]), F1=csub(a[0],a[4]);
    float2 G0=cadd(a[2],a[6]), G1=csub(a[2],a[6]);
    float2 H0=cadd(a[1],a[5]), H1=csub(a[1],a[5]);
    float2 K0=cadd(a[3],a[7]), K1=csub(a[3],a[7]);
    float2 E0=cadd(F0,G0), E2=csub(F0,G0);
    float2 E1=make_float2(F1.x-G1.y, F1.y+G1.x);   // F1 + i G1
    float2 E3=make_float2(F1.x+G1.y, F1.y-G1.x);   // F1 - i G1
    float2 O0=cadd(H0,K0), O2=csub(H0,K0);
    float2 O1=make_float2(H1.x-K1.y, H1.y+K1.x);
    float2 O3=make_float2(H1.x+K1.y, H1.y-K1.x);
    float2 t1=make_float2(RC8*(O1.x-O1.y),  RC8*(O1.x+O1.y));   // conj(w8)^1 * O1
    float2 t2=make_float2(-O2.y, O2.x);                          // +i O2
    float2 t3=make_float2(-RC8*(O3.x+O3.y), RC8*(O3.x-O3.y));   // conj(w8^3) * O3
    a[0]=cadd(E0,O0); a[4]=csub(E0,O0);
    a[1]=cadd(E1,t1); a[5]=csub(E1,t1);
    a[2]=cadd(E2,t2); a[6]=csub(E2,t2);
    a[3]=cadd(E3,t3); a[7]=csub(E3,t3);
}

// 8-point DFT with a[4..7] == 0 implied; inputs a[0..3]
__device__ __forceinline__ void fwd8h(float2* a) {
    float2 a0=a[0], a1=a[1], a2=a[2], a3=a[3];
    float2 E0=cadd(a0,a2), E2=csub(a0,a2);
    float2 E1=make_float2(a0.x+a2.y, a0.y-a2.x);
    float2 E3=make_float2(a0.x-a2.y, a0.y+a2.x);
    float2 O0=cadd(a1,a3), O2=csub(a1,a3);
    float2 O1=make_float2(a1.x+a3.y, a1.y-a3.x);
    float2 O3=make_float2(a1.x-a3.y, a1.y+a3.x);
    float2 t1=make_float2(RC8*(O1.x+O1.y),  RC8*(O1.y-O1.x));
    float2 t2=make_float2(O2.y, -O2.x);
    float2 t3=make_float2(RC8*(O3.y-O3.x), -RC8*(O3.x+O3.y));
    a[0]=cadd(E0,O0); a[4]=csub(E0,O0);
    a[1]=cadd(E1,t1); a[5]=csub(E1,t1);
    a[2]=cadd(E2,t2); a[6]=csub(E2,t2);
    a[3]=cadd(E3,t3); a[7]=csub(E3,t3);
}

// y[r] *= w1^r  (forward external twiddle)
__device__ __forceinline__ void twid_fwd(float2* y, float2 w1) {
    float2 w2=cmul(w1,w1), w3=cmul(w2,w1), w4=cmul(w2,w2);
    float2 w5=cmul(w3,w2), w6=cmul(w3,w3), w7=cmul(w4,w3);
    y[1]=cmul(y[1],w1); y[2]=cmul(y[2],w2); y[3]=cmul(y[3],w3); y[4]=cmul(y[4],w4);
    y[5]=cmul(y[5],w5); y[6]=cmul(y[6],w6); y[7]=cmul(y[7],w7);
}
// y[r] *= conj(w1^r)  (inverse external twiddle)
__device__ __forceinline__ void twid_inv(float2* y, float2 w1) {
    float2 w2=cmul(w1,w1), w3=cmul(w2,w1), w4=cmul(w2,w2);
    float2 w5=cmul(w3,w2), w6=cmul(w3,w3), w7=cmul(w4,w3);
    y[1]=cmulc(y[1],w1); y[2]=cmulc(y[2],w2); y[3]=cmulc(y[3],w3); y[4]=cmulc(y[4],w4);
    y[5]=cmulc(y[5],w5); y[6]=cmulc(y[6],w6); y[7]=cmulc(y[7],w7);
}

// ---------------- precompute kernels ----------------
__global__ void k_tables() {
    int i = blockIdx.x * blockDim.x + threadIdx.x;
    if (i >= 2048) return;
    float s, c;
    sincospif((float)i / 2048.0f, &s, &c);
    g_tw[i] = make_float2(c, -s);
    long long j = i;
    long long idxU = (2LL * j * M0C + j * j) % (2LL * NF);
    sincospif((float)idxU / (float)NF, &s, &c);
    g_phaseU[i] = make_float2(c, s);
    long long e2 = (2LL * (T - 1) * (M0C + j) + j * j) % NF;
    sincospif(2.0f * (float)e2 / (float)NF, &s, &c);
    g_psi[i] = make_float2(c, s);
}

// shared carve (same for k_W and k_main): tw 2048 | Z 2048 | buf 4672 | t512 64 | t64 8 | t256 32 | t32 4
#define SMEM_F2 (2048 + 2048 + 4672 + 64 + 8 + 32 + 4)

__device__ __forceinline__ void load_tables(float2* s_tw, float2* s_t512, float2* s_t64,
                                            float2* s_t256, float2* s_t32) {
    int t = threadIdx.x, nt = blockDim.x;
    for (int k = t; k < 2048; k += nt) s_tw[k] = g_tw[k];
    if (t < 64) s_t512[t] = g_tw[8 * t];
    if (t < 8)  s_t64[t]  = g_tw[64 * t];
    if (t < 32) s_t256[t] = g_tw[16 * t];
    if (t < 4)  s_t32[t]  = g_tw[128 * t];
}

// forward 4096 stages 2..4 operating on padded s_buf; stage4 leaves y in regs of caller? (k_W stores)
extern __shared__ float2 smem_c[];

__global__ void k_W() {
    float2* s_tw   = smem_c;
    float2* s_buf  = smem_c + 4096;
    float2* s_t512 = s_buf + 4672;
    float2* s_t64  = s_t512 + 64;
    float2* s_t256 = s_t64 + 8;
    float2* s_t32  = s_t256 + 32;
    int t = threadIdx.x;
    load_tables(s_tw, s_t512, s_t64, s_t256, s_t32);
    for (int n = t; n < 4096; n += blockDim.x) {
        float2 v;
        if (n == 2048) v = make_float2(0.f, 0.f);
        else {
            long long k = (n < 2048) ? n : (4096 - n);
            long long idx = (k * k) % (2LL * NF);
            float s, c;
            sincospif((float)idx / (float)NF, &s, &c);
            v = make_float2(c, -s);
        }
        s_buf[PAD(n)] = v;
    }
    __syncthreads();
    float2 a[8];
    // stage1: S=4096 q=512
#pragma unroll
    for (int j = 0; j < 8; j++) a[j] = s_buf[PAD(t + 512 * j)];
    fwd8(a); twid_fwd(a, s_tw[t]);
    __syncthreads();
#pragma unroll
    for (int r = 0; r < 8; r++) s_buf[PAD(512 * r + t)] = a[r];
    __syncthreads();
    // stage2: S=512 q=64
    {
        int s2 = t >> 6, k = t & 63, base = 512 * s2;
#pragma unroll
        for (int j = 0; j < 8; j++) a[j] = s_buf[PAD(base + k + 64 * j)];
        fwd8(a); twid_fwd(a, s_t512[k]);
        __syncthreads();
#pragma unroll
        for (int r = 0; r < 8; r++) s_buf[PAD(base + 64 * r + k)] = a[r];
        __syncthreads();
    }
    // stage3: S=64 q=8
    {
        int b3 = t >> 3, k = t & 7, base = 64 * b3;
#pragma unroll
        for (int j = 0; j < 8; j++) a[j] = s_buf[PAD(base + k + 8 * j)];
        fwd8(a); twid_fwd(a, s_t64[k]);
        __syncthreads();
#pragma unroll
        for (int r = 0; r < 8; r++) s_buf[PAD(base + 8 * r + k)] = a[r];
        __syncthreads();
    }
    // stage4: S=8 q=1, store
#pragma unroll
    for (int j = 0; j < 8; j++) a[j] = s_buf[PAD(8 * t + j)];
    fwd8(a);
#pragma unroll
    for (int r = 0; r < 8; r++) g_W[8 * t + r] = a[r];
}

struct FnnW { const float *w1, *b1, *w2, *b2; };

__global__ void k_fnn(FnnW wf, FnnW wg, FnnW wfp, FnnW wgp) {
    int i = blockIdx.x * blockDim.x + threadIdx.x;
    if (i >= 4 * 2048) return;
    int q = i >> 11, p = i & 2047;
    FnnW W = (q == 0) ? wf : (q == 1) ? wg : (q == 2) ? wfp : wgp;
    float x = (q == 0 || q == 2) ? (float)(T - 1 - p) : (float)p;
    float z = W.b2[0];
#pragma unroll
    for (int h = 0; h < 5; h++)
        z += W.w2[h] * tanhf(W.w1[h] * x + W.b1[h]);
    g_q[i] = z * expf(-5.0f * x);
}

__global__ void k_H() {
    int gw = (blockIdx.x * blockDim.x + threadIdx.x) >> 5;
    int lane = threadIdx.x & 31;
    if (gw >= 4 * 2048) return;
    int q = gw >> 11, j = gw & 2047;
    long long base = j + (T - 1);
    long long idx0 = (base * (long long)(lane + T - 1)) % NF;
    float s, c;
    sincospif(2.0f * (float)idx0 / (float)NF, &s, &c);
    float2 ph = make_float2(c, -s);
    long long idxs = (base * 32LL) % NF;
    sincospif(2.0f * (float)idxs / (float)NF, &s, &c);
    float2 st = make_float2(c, -s);
    float2 acc = make_float2(0.f, 0.f);
    const float* qq = g_q + q * 2048;
#pragma unroll 8
    for (int it = 0; it < 64; it++) {
        float v = qq[lane + 32 * it];
        acc.x = fmaf(v, ph.x, acc.x);
        acc.y = fmaf(v, ph.y, acc.y);
        ph = cmul(ph, st);
    }
    for (int off = 16; off; off >>= 1) {
        acc.x += __shfl_down_sync(0xffffffffu, acc.x, off);
        acc.y += __shfl_down_sync(0xffffffffu, acc.y, off);
    }
    if (lane == 0) g_UH[q * 2048 + j] = cmul(acc, g_phaseU[j]);
}

// ---------------- rotation prefix scan (unchanged) ----------------
__device__ __forceinline__ void rod(float vx, float vy, float vz, float* M) {
    float t2 = vx * vx + vy * vy + vz * vz;
    float th = sqrtf(t2);
    float a, bb;
    if (t2 < 1e-8f) { a = 1.0f - t2 * (1.0f / 6.0f); bb = 0.5f - t2 * (1.0f / 24.0f); }
    else { a = sinf(th) / th; float sh = sinf(0.5f * th); bb = 2.0f * sh * sh / t2; }
    float ct = 1.0f - bb * t2;
    M[0] = ct + bb * vx * vx; M[1] = bb * vx * vy - a * vz; M[2] = bb * vx * vz + a * vy;
    M[3] = bb * vy * vx + a * vz; M[4] = ct + bb * vy * vy; M[5] = bb * vy * vz - a * vx;
    M[6] = bb * vz * vx - a * vy; M[7] = bb * vz * vy + a * vx; M[8] = ct + bb * vz * vz;
}
__device__ __forceinline__ void mm3(const float* A, const float* B, float* C) {
    float t[9];
#pragma unroll
    for (int i = 0; i < 3; i++)
#pragma unroll
        for (int j = 0; j < 3; j++)
            t[3 * i + j] = A[3 * i] * B[j] + A[3 * i + 1] * B[3 + j] + A[3 * i + 2] * B[6 + j];
#pragma unroll
    for (int k = 0; k < 9; k++) C[k] = t[k];
}
__device__ __forceinline__ void inv3(const float* A, float* B) {
    float c00 = A[4] * A[8] - A[5] * A[7];
    float c01 = A[5] * A[6] - A[3] * A[8];
    float c02 = A[3] * A[7] - A[4] * A[6];
    float id = 1.0f / (A[0] * c00 + A[1] * c01 + A[2] * c02);
    B[0] = c00 * id; B[1] = (A[2] * A[7] - A[1] * A[8]) * id; B[2] = (A[1] * A[5] - A[2] * A[4]) * id;
    B[3] = c01 * id; B[4] = (A[0] * A[8] - A[2] * A[6]) * id; B[5] = (A[2] * A[3] - A[0] * A[5]) * id;
    B[6] = c02 * id; B[7] = (A[1] * A[6] - A[0] * A[7]) * id; B[8] = (A[0] * A[4] - A[1] * A[3]) * id;
}
__global__ void k_scan(const float* __restrict__ xd,
                       const float* __restrict__ A1, const float* __restrict__ A2) {
    __shared__ float sP[256][9];
    __shared__ float sv[6];
    int b = blockIdx.x, tid = threadIdx.x;
    if (tid == 0) {
        sv[0] = A1[7] - A1[5]; sv[1] = A1[2] - A1[6]; sv[2] = A1[3] - A1[1];
        sv[3] = A2[7] - A2[5]; sv[4] = A2[2] - A2[6]; sv[5] = A2[3] - A2[1];
    }
    __syncthreads();
    float v1x = sv[0], v1y = sv[1], v1z = sv[2], v2x = sv[3], v2y = sv[4], v2z = sv[5];
    float P[9] = {1, 0, 0, 0, 1, 0, 0, 0, 1};
    int t0 = tid * 8;
    for (int tt = 0; tt < 8; tt++) {
        int t = t0 + tt;
        if (t == 0) continue;
        float z1 = xd[(b * T + t) * 2], z2 = xd[(b * T + t) * 2 + 1];
        float M[9];
        rod(z1 * v1x + z2 * v2x, z1 * v1y + z2 * v2y, z1 * v1z + z2 * v2z, M);
        mm3(P, M, P);
    }
    float mine[9];
#pragma unroll
    for (int k = 0; k < 9; k++) { mine[k] = P[k]; sP[tid][k] = P[k]; }
    __syncthreads();
    for (int off = 1; off < 256; off <<= 1) {
        float Lm[9];
        bool act = (tid >= off);
        if (act)
#pragma unroll
            for (int k = 0; k < 9; k++) Lm[k] = sP[tid - off][k];
        __syncthreads();
        if (act) {
            mm3(Lm, mine, mine);
#pragma unroll
            for (int k = 0; k < 9; k++) sP[tid][k] = mine[k];
        }
        __syncthreads();
    }
    float X[9] = {1, 0, 0, 0, 1, 0, 0, 0, 1};
    if (tid > 0)
#pragma unroll
        for (int k = 0; k < 9; k++) X[k] = sP[tid - 1][k];
    for (int tt = 0; tt < 8; tt++) {
        int t = t0 + tt;
        if (t != 0) {
            float z1 = xd[(b * T + t) * 2], z2 = xd[(b * T + t) * 2 + 1];
            float M[9];
            rod(z1 * v1x + z2 * v2x, z1 * v1y + z2 * v2y, z1 * v1z + z2 * v2z, M);
            mm3(X, M, X);
        }
        float Bi[9];
        inv3(X, Bi);
#pragma unroll
        for (int c = 0; c < 9; c++) {
            g_A[(c * BATCH + b) * T + t] = X[c];
            g_B[(c * BATCH + b) * T + t] = Bi[c];
        }
    }
}

// ---------------- main kernel ----------------
__global__ __launch_bounds__(512, 2) void k_main(float* __restrict__ out) {
    float2* s_tw   = smem_c;           // 2048
    float2* s_Z    = smem_c + 2048;    // 2048
    float2* s_buf  = smem_c + 4096;    // 4672 (padded 4096)
    float2* s_t512 = s_buf + 4672;
    float2* s_t64  = s_t512 + 64;
    float2* s_t256 = s_t64 + 8;
    float2* s_t32  = s_t256 + 32;

    int b = blockIdx.x / 9, c = blockIdx.x % 9;
    int t = threadIdx.x;

    load_tables(s_tw, s_t512, s_t64, s_t256, s_t32);
    __syncthreads();

    const float* Ar = g_A + (c * BATCH + b) * T;
    const float* Ai = g_B + (c * BATCH + b) * T;

    // ===== phase 0: packed 2048-point FFT (256 active threads) =====
    float2 a[8];
    if (t < 256) {
#pragma unroll
        for (int j = 0; j < 8; j++) {
            int i = t + 256 * j;
            a[j] = make_float2(Ai[i], Ar[i]);   // z = Xir + i*Xr
        }
        fwd8(a); twid_fwd(a, s_tw[2 * t]);      // e^{-2pi i t/2048}
    }
    __syncthreads();
    if (t < 256) {
#pragma unroll
        for (int r = 0; r < 8; r++) s_buf[PAD(256 * r + t)] = a[r];
    }
    __syncthreads();
    int p_base, p_k;
    if (t < 256) {  // stage2: S=256 q=32
        p_base = 256 * (t >> 5); p_k = t & 31;
#pragma unroll
        for (int j = 0; j < 8; j++) a[j] = s_buf[PAD(p_base + p_k + 32 * j)];
        fwd8(a); twid_fwd(a, s_t256[p_k]);
    }
    __syncthreads();
    if (t < 256) {
#pragma unroll
        for (int r = 0; r < 8; r++) s_buf[PAD(p_base + 32 * r + p_k)] = a[r];
    }
    __syncthreads();
    if (t < 256) {  // stage3: S=32 q=4
        p_base = 32 * (t >> 2); p_k = t & 3;
#pragma unroll
        for (int j = 0; j < 8; j++) a[j] = s_buf[PAD(p_base + p_k + 4 * j)];
        fwd8(a); twid_fwd(a, s_t32[p_k]);
    }
    __syncthreads();
    if (t < 256) {
#pragma unroll
        for (int r = 0; r < 8; r++) s_buf[PAD(p_base + 4 * r + p_k)] = a[r];
    }
    __syncthreads();
    if (t < 256) {  // stage4: radix-4, 2 blocks/thread, unscramble to natural order
#pragma unroll
        for (int h = 0; h < 2; h++) {
            int B = 2 * t + h;
            float2 b4[4];
#pragma unroll
            for (int j = 0; j < 4; j++) b4[j] = s_buf[PAD(4 * B + j)];
            float2 e0 = cadd(b4[0], b4[2]), e1 = csub(b4[0], b4[2]);
            float2 o0 = cadd(b4[1], b4[3]), o1 = csub(b4[1], b4[3]);
            float2 y0 = cadd(e0, o0), y2 = csub(e0, o0);
            float2 y1 = make_float2(e1.x + o1.y, e1.y - o1.x);
            float2 y3 = make_float2(e1.x - o1.y, e1.y + o1.x);
            int f = (B >> 6) + 8 * ((B >> 3) & 7) + 64 * (B & 7);
            s_Z[f] = y0; s_Z[f + 512] = y1; s_Z[f + 1024] = y2; s_Z[f + 1536] = y3;
        }
    }
    __syncthreads();

    // ===== chirp rounds =====
    float2 c1r[4], Pr[4];
    const float sc = 1.0f / (4096.0f * (float)NF);
    const int s2i = t >> 6, k2 = t & 63, base2 = 512 * s2i;
    const int b3i = t >> 3, k3 = t & 7, base3 = 64 * b3i;

    for (int s = 0; s < 4; s++) {
        bool useIr = (s == 0 || s == 2);
        const float2* UH = g_UH + s * 2048;

        // fwd stage1 (gen from s_Z, half-zero input)
#pragma unroll
        for (int j = 0; j < 4; j++) {
            int i = t + 512 * j;
            float2 Zj = s_Z[i], Zm = s_Z[(2048 - i) & 2047];
            float2 X = useIr
                ? make_float2(0.5f * (Zj.x + Zm.x), 0.5f * (Zj.y - Zm.y))
                : make_float2(0.5f * (Zj.y + Zm.y), 0.5f * (Zm.x - Zj.x));
            a[j] = cmul(X, UH[i]);
        }
        fwd8h(a); twid_fwd(a, s_tw[t]);
        __syncthreads();
#pragma unroll
        for (int r = 0; r < 8; r++) s_buf[PAD(512 * r + t)] = a[r];
        __syncthreads();

        // fwd stage2
#pragma unroll
        for (int j = 0; j < 8; j++) a[j] = s_buf[PAD(base2 + k2 + 64 * j)];
        fwd8(a); twid_fwd(a, s_t512[k2]);
        __syncthreads();
#pragma unroll
        for (int r = 0; r < 8; r++) s_buf[PAD(base2 + 64 * r + k2)] = a[r];
        __syncthreads();

        // fwd stage3
#pragma unroll
        for (int j = 0; j < 8; j++) a[j] = s_buf[PAD(base3 + k3 + 8 * j)];
        fwd8(a); twid_fwd(a, s_t64[k3]);
        __syncthreads();
#pragma unroll
        for (int r = 0; r < 8; r++) s_buf[PAD(base3 + 8 * r + k3)] = a[r];
        __syncthreads();

        // fwd stage4 + W pointwise + inv stage4 (all in registers, no exchange)
#pragma unroll
        for (int j = 0; j < 8; j++) a[j] = s_buf[PAD(8 * t + j)];
        fwd8(a);
        {
            const float4* W4 = (const float4*)(g_W + 8 * t);
            float4 w = W4[0];
            a[0] = cmul(a[0], make_float2(w.x, w.y)); a[1] = cmul(a[1], make_float2(w.z, w.w));
            w = W4[1];
            a[2] = cmul(a[2], make_float2(w.x, w.y)); a[3] = cmul(a[3], make_float2(w.z, w.w));
            w = W4[2];
            a[4] = cmul(a[4], make_float2(w.x, w.y)); a[5] = cmul(a[5], make_float2(w.z, w.w));
            w = W4[3];
            a[6] = cmul(a[6], make_float2(w.x, w.y)); a[7] = cmul(a[7], make_float2(w.z, w.w));
        }
        inv8(a);
        __syncthreads();
#pragma unroll
        for (int j = 0; j < 8; j++) s_buf[PAD(8 * t + j)] = a[j];
        __syncthreads();

        // inv stage3
#pragma unroll
        for (int r = 0; r < 8; r++) a[r] = s_buf[PAD(base3 + 8 * r + k3)];
        twid_inv(a, s_t64[k3]); inv8(a);
        __syncthreads();
#pragma unroll
        for (int j = 0; j < 8; j++) s_buf[PAD(base3 + k3 + 8 * j)] = a[j];
        __syncthreads();

        // inv stage2
#pragma unroll
        for (int r = 0; r < 8; r++) a[r] = s_buf[PAD(base2 + 64 * r + k2)];
        twid_inv(a, s_t512[k2]); inv8(a);
        __syncthreads();
#pragma unroll
        for (int j = 0; j < 8; j++) s_buf[PAD(base2 + k2 + 64 * j)] = a[j];
        __syncthreads();

        // inv stage1 (only outputs m = t + 512j, j<4) -> registers
#pragma unroll
        for (int r = 0; r < 8; r++) a[r] = s_buf[PAD(512 * r + t)];
        twid_inv(a, s_tw[t]); inv8(a);
#pragma unroll
        for (int j = 0; j < 4; j++) {
            float2 v = make_float2(a[j].x * sc, a[j].y * sc);
            if (s == 0) c1r[j] = v;
            else if (s == 1) Pr[j] = cmul(c1r[j], v);
            else if (s == 2) c1r[j] = v;
            else {
                float2 p = cmul(c1r[j], v);
                Pr[j].x += p.x; Pr[j].y += p.y;
            }
        }
        __syncthreads();
    }

#pragma unroll
    for (int j = 0; j < 4; j++) {
        int m = t + 512 * j;
        float2 psi = g_psi[m];
        out[(b * T + m) * 9 + c] = Pr[j].x * psi.x - Pr[j].y * psi.y;
    }
}

// ---------------- launch ----------------
extern "C" void kernel_launch(void* const* d_in, const int* in_sizes, int n_in,
                              void* d_out, int out_size) {
    const float* xd = (const float*)d_in[0];
    const float* A1 = (const float*)d_in[1];
    const float* A2 = (const float*)d_in[2];
    FnnW wf  = {(const float*)d_in[3],  (const float*)d_in[4],  (const float*)d_in[5],  (const float*)d_in[6]};
    FnnW wg  = {(const float*)d_in[7],  (const float*)d_in[8],  (const float*)d_in[9],  (const float*)d_in[10]};
    FnnW wfp = {(const float*)d_in[11], (const float*)d_in[12], (const float*)d_in[13], (const float*)d_in[14]};
    FnnW wgp = {(const float*)d_in[15], (const float*)d_in[16], (const float*)d_in[17], (const float*)d_in[18]};
    float* out = (float*)d_out;

    int smem_bytes = SMEM_F2 * sizeof(float2);
    cudaFuncSetAttribute(k_main, cudaFuncAttributeMaxDynamicSharedMemorySize, smem_bytes);
    cudaFuncSetAttribute(k_W,    cudaFuncAttributeMaxDynamicSharedMemorySize, smem_bytes);

    k_tables<<<8, 256>>>();
    k_fnn<<<32, 256>>>(wf, wg, wfp, wgp);
    k_W<<<1, 512, smem_bytes>>>();
    k_H<<<1024, 256>>>();
    k_scan<<<BATCH, 256>>>(xd, A1, A2);
    k_main<<<BATCH * 9, 512, smem_bytes>>>(out);
}

// round 4
// speedup vs baseline: 3.5985x; 1.1001x over previous
#include <cuda_runtime.h>
#include <math.h>

#define T    2048
#define NF   6142     // 3T-2
#define M0C  4094     // 2T-2
#define BATCH 64

// ---------------- device scratch ----------------
__device__ float2 g_tw[2048];        // e^{-2pi i k/4096}
__device__ float2 g_psi[2048];
__device__ float2 g_W[4096];         // digit-ordered FFT of chirp
__device__ float2 g_UH[4 * 2048];    // Htilde * phaseU
__device__ float  g_A[9 * BATCH * T];
__device__ float  g_B[9 * BATCH * T];

__device__ __forceinline__ float2 cmul(float2 a, float2 b) {
    return make_float2(fmaf(a.x, b.x, -a.y * b.y), fmaf(a.x, b.y, a.y * b.x));
}
__device__ __forceinline__ float2 cmulc(float2 a, float2 b) {  // a * conj(b)
    return make_float2(fmaf(a.x, b.x, a.y * b.y), fmaf(a.y, b.x, -a.x * b.y));
}
__device__ __forceinline__ float2 cadd(float2 a, float2 b) { return make_float2(a.x + b.x, a.y + b.y); }
__device__ __forceinline__ float2 csub(float2 a, float2 b) { return make_float2(a.x - b.x, a.y - b.y); }
__device__ __forceinline__ int PAD(int e) { return e + (e >> 3) + (e >> 6); }

#define RC8 0.70710678118654752440f

__device__ __forceinline__ void fwd8(float2* a) {
    float2 F0=cadd(a[0],a[4]), F1=csub(a[0],a[4]);
    float2 G0=cadd(a[2],a[6]), G1=csub(a[2],a[6]);
    float2 H0=cadd(a[1],a[5]), H1=csub(a[1],a[5]);
    float2 K0=cadd(a[3],a[7]), K1=csub(a[3],a[7]);
    float2 E0=cadd(F0,G0), E2=csub(F0,G0);
    float2 E1=make_float2(F1.x+G1.y, F1.y-G1.x);
    float2 E3=make_float2(F1.x-G1.y, F1.y+G1.x);
    float2 O0=cadd(H0,K0), O2=csub(H0,K0);
    float2 O1=make_float2(H1.x+K1.y, H1.y-K1.x);
    float2 O3=make_float2(H1.x-K1.y, H1.y+K1.x);
    float2 t1=make_float2(RC8*(O1.x+O1.y),  RC8*(O1.y-O1.x));
    float2 t2=make_float2(O2.y, -O2.x);
    float2 t3=make_float2(RC8*(O3.y-O3.x), -RC8*(O3.x+O3.y));
    a[0]=cadd(E0,O0); a[4]=csub(E0,O0);
    a[1]=cadd(E1,t1); a[5]=csub(E1,t1);
    a[2]=cadd(E2,t2); a[6]=csub(E2,t2);
    a[3]=cadd(E3,t3); a[7]=csub(E3,t3);
}

__device__ __forceinline__ void inv8(float2* a) {
    float2 F0=cadd(a[0],a[4]), F1=csub(a[0],a[4]);
    float2 G0=cadd(a[2],a[6]), G1=csub(a[2],a[6]);
    float2 H0=cadd(a[1],a[5]), H1=csub(a[1],a[5]);
    float2 K0=cadd(a[3],a[7]), K1=csub(a[3],a[7]);
    float2 E0=cadd(F0,G0), E2=csub(F0,G0);
    float2 E1=make_float2(F1.x-G1.y, F1.y+G1.x);
    float2 E3=make_float2(F1.x+G1.y, F1.y-G1.x);
    float2 O0=cadd(H0,K0), O2=csub(H0,K0);
    float2 O1=make_float2(H1.x-K1.y, H1.y+K1.x);
    float2 O3=make_float2(H1.x+K1.y, H1.y-K1.x);
    float2 t1=make_float2(RC8*(O1.x-O1.y),  RC8*(O1.x+O1.y));
    float2 t2=make_float2(-O2.y, O2.x);
    float2 t3=make_float2(-RC8*(O3.x+O3.y), RC8*(O3.x-O3.y));
    a[0]=cadd(E0,O0); a[4]=csub(E0,O0);
    a[1]=cadd(E1,t1); a[5]=csub(E1,t1);
    a[2]=cadd(E2,t2); a[6]=csub(E2,t2);
    a[3]=cadd(E3,t3); a[7]=csub(E3,t3);
}

__device__ __forceinline__ void fwd8h(float2* a) {  // a[4..7] implied zero
    float2 a0=a[0], a1=a[1], a2=a[2], a3=a[3];
    float2 E0=cadd(a0,a2), E2=csub(a0,a2);
    float2 E1=make_float2(a0.x+a2.y, a0.y-a2.x);
    float2 E3=make_float2(a0.x-a2.y, a0.y+a2.x);
    float2 O0=cadd(a1,a3), O2=csub(a1,a3);
    float2 O1=make_float2(a1.x+a3.y, a1.y-a3.x);
    float2 O3=make_float2(a1.x-a3.y, a1.y+a3.x);
    float2 t1=make_float2(RC8*(O1.x+O1.y),  RC8*(O1.y-O1.x));
    float2 t2=make_float2(O2.y, -O2.x);
    float2 t3=make_float2(RC8*(O3.y-O3.x), -RC8*(O3.x+O3.y));
    a[0]=cadd(E0,O0); a[4]=csub(E0,O0);
    a[1]=cadd(E1,t1); a[5]=csub(E1,t1);
    a[2]=cadd(E2,t2); a[6]=csub(E2,t2);
    a[3]=cadd(E3,t3); a[7]=csub(E3,t3);
}

__device__ __forceinline__ void twid_fwd(float2* y, float2 w1) {
    float2 w2=cmul(w1,w1), w3=cmul(w2,w1), w4=cmul(w2,w2);
    float2 w5=cmul(w3,w2), w6=cmul(w3,w3), w7=cmul(w4,w3);
    y[1]=cmul(y[1],w1); y[2]=cmul(y[2],w2); y[3]=cmul(y[3],w3); y[4]=cmul(y[4],w4);
    y[5]=cmul(y[5],w5); y[6]=cmul(y[6],w6); y[7]=cmul(y[7],w7);
}
__device__ __forceinline__ void twid_inv(float2* y, float2 w1) {
    float2 w2=cmul(w1,w1), w3=cmul(w2,w1), w4=cmul(w2,w2);
    float2 w5=cmul(w3,w2), w6=cmul(w3,w3), w7=cmul(w4,w3);
    y[1]=cmulc(y[1],w1); y[2]=cmulc(y[2],w2); y[3]=cmulc(y[3],w3); y[4]=cmulc(y[4],w4);
    y[5]=cmulc(y[5],w5); y[6]=cmulc(y[6],w6); y[7]=cmulc(y[7],w7);
}

// ---------------- 3x3 helpers ----------------
__device__ __forceinline__ void rod(float vx, float vy, float vz, float* M) {
    float t2 = vx * vx + vy * vy + vz * vz;
    float th = sqrtf(t2);
    float a, bb;
    if (t2 < 1e-8f) { a = 1.0f - t2 * (1.0f / 6.0f); bb = 0.5f - t2 * (1.0f / 24.0f); }
    else { a = sinf(th) / th; float sh = sinf(0.5f * th); bb = 2.0f * sh * sh / t2; }
    float ct = 1.0f - bb * t2;
    M[0] = ct + bb * vx * vx; M[1] = bb * vx * vy - a * vz; M[2] = bb * vx * vz + a * vy;
    M[3] = bb * vy * vx + a * vz; M[4] = ct + bb * vy * vy; M[5] = bb * vy * vz - a * vx;
    M[6] = bb * vz * vx - a * vy; M[7] = bb * vz * vy + a * vx; M[8] = ct + bb * vz * vz;
}
__device__ __forceinline__ void mm3(const float* A, const float* B, float* C) {
    float t[9];
#pragma unroll
    for (int i = 0; i < 3; i++)
#pragma unroll
        for (int j = 0; j < 3; j++)
            t[3 * i + j] = A[3 * i] * B[j] + A[3 * i + 1] * B[3 + j] + A[3 * i + 2] * B[6 + j];
#pragma unroll
    for (int k = 0; k < 9; k++) C[k] = t[k];
}
__device__ __forceinline__ void inv3(const float* A, float* B) {
    float c00 = A[4] * A[8] - A[5] * A[7];
    float c01 = A[5] * A[6] - A[3] * A[8];
    float c02 = A[3] * A[7] - A[4] * A[6];
    float id = 1.0f / (A[0] * c00 + A[1] * c01 + A[2] * c02);
    B[0] = c00 * id; B[1] = (A[2] * A[7] - A[1] * A[8]) * id; B[2] = (A[1] * A[5] - A[2] * A[4]) * id;
    B[3] = c01 * id; B[4] = (A[0] * A[8] - A[2] * A[6]) * id; B[5] = (A[2] * A[3] - A[0] * A[5]) * id;
    B[6] = c02 * id; B[7] = (A[1] * A[6] - A[0] * A[7]) * id; B[8] = (A[0] * A[4] - A[1] * A[3]) * id;
}

struct FnnW { const float *w1, *b1, *w2, *b2; };

extern __shared__ float2 smem_c[];

// ================= fused precompute kernel =================
// blocks 0..63: rotation prefix scan (b = blk)
// blocks 64..67: twiddle + psi tables
// block  68:     g_W (chirp FFT; self-contained twiddles)
// blocks 69..580: g_UH (H blocks; each computes its filter's FNN row locally)
__global__ __launch_bounds__(512) void k_pre(
    const float* __restrict__ xd, const float* __restrict__ A1, const float* __restrict__ A2,
    FnnW wf, FnnW wg, FnnW wfp, FnnW wgp)
{
    int blk = blockIdx.x, tid = threadIdx.x;

    if (blk < 64) {
        // ---------------- scan role (256 active threads) ----------------
        float* sP = (float*)smem_c;        // 256*9
        float* sv = sP + 2304;             // 6
        int b = blk;
        if (tid == 0) {
            sv[0] = A1[7] - A1[5]; sv[1] = A1[2] - A1[6]; sv[2] = A1[3] - A1[1];
            sv[3] = A2[7] - A2[5]; sv[4] = A2[2] - A2[6]; sv[5] = A2[3] - A2[1];
        }
        __syncthreads();
        float v1x = sv[0], v1y = sv[1], v1z = sv[2], v2x = sv[3], v2y = sv[4], v2z = sv[5];
        bool act = tid < 256;
        float mine[9];
        int t0 = tid * 8;
        if (act) {
            float P[9] = {1, 0, 0, 0, 1, 0, 0, 0, 1};
            for (int tt = 0; tt < 8; tt++) {
                int t = t0 + tt;
                if (t == 0) continue;
                float z1 = xd[(b * T + t) * 2], z2 = xd[(b * T + t) * 2 + 1];
                float M[9];
                rod(z1 * v1x + z2 * v2x, z1 * v1y + z2 * v2y, z1 * v1z + z2 * v2z, M);
                mm3(P, M, P);
            }
#pragma unroll
            for (int k = 0; k < 9; k++) { mine[k] = P[k]; sP[tid * 9 + k] = P[k]; }
        }
        __syncthreads();
        for (int off = 1; off < 256; off <<= 1) {
            float Lm[9];
            bool a2 = act && tid >= off;
            if (a2)
#pragma unroll
                for (int k = 0; k < 9; k++) Lm[k] = sP[(tid - off) * 9 + k];
            __syncthreads();
            if (a2) {
                mm3(Lm, mine, mine);
#pragma unroll
                for (int k = 0; k < 9; k++) sP[tid * 9 + k] = mine[k];
            }
            __syncthreads();
        }
        if (act) {
            float X[9] = {1, 0, 0, 0, 1, 0, 0, 0, 1};
            if (tid > 0)
#pragma unroll
                for (int k = 0; k < 9; k++) X[k] = sP[(tid - 1) * 9 + k];
            for (int tt = 0; tt < 8; tt++) {
                int t = t0 + tt;
                if (t != 0) {
                    float z1 = xd[(b * T + t) * 2], z2 = xd[(b * T + t) * 2 + 1];
                    float M[9];
                    rod(z1 * v1x + z2 * v2x, z1 * v1y + z2 * v2y, z1 * v1z + z2 * v2z, M);
                    mm3(X, M, X);
                }
                float Bi[9];
                inv3(X, Bi);
#pragma unroll
                for (int c = 0; c < 9; c++) {
                    g_A[(c * BATCH + b) * T + t] = X[c];
                    g_B[(c * BATCH + b) * T + t] = Bi[c];
                }
            }
        }
    } else if (blk < 68) {
        // ---------------- tables role ----------------
        int i = (blk - 64) * 512 + tid;
        float s, c;
        sincospif((float)i / 2048.0f, &s, &c);
        g_tw[i] = make_float2(c, -s);
        long long j = i;
        long long e2 = (2LL * (T - 1) * (M0C + j) + j * j) % NF;
        sincospif(2.0f * (float)e2 / (float)NF, &s, &c);
        g_psi[i] = make_float2(c, s);
    } else if (blk == 68) {
        // ---------------- W role (self-contained) ----------------
        float2* s_tw   = smem_c;
        float2* s_buf  = smem_c + 2048;
        float2* s_t512 = s_buf + 4672;
        float2* s_t64  = s_t512 + 64;
        int t = tid;
        for (int i = t; i < 2048; i += 512) {
            float s, c;
            sincospif((float)i / 2048.0f, &s, &c);
            s_tw[i] = make_float2(c, -s);
        }
        __syncthreads();
        if (t < 64) s_t512[t] = s_tw[8 * t];
        if (t < 8)  s_t64[t]  = s_tw[64 * t];
        for (int n = t; n < 4096; n += 512) {
            float2 v;
            if (n == 2048) v = make_float2(0.f, 0.f);
            else {
                long long k = (n < 2048) ? n : (4096 - n);
                long long idx = (k * k) % (2LL * NF);
                float s, c;
                sincospif((float)idx / (float)NF, &s, &c);
                v = make_float2(c, -s);
            }
            s_buf[PAD(n)] = v;
        }
        __syncthreads();
        float2 a[8];
#pragma unroll
        for (int j = 0; j < 8; j++) a[j] = s_buf[PAD(t + 512 * j)];
        fwd8(a); twid_fwd(a, s_tw[t]);
        __syncthreads();
#pragma unroll
        for (int r = 0; r < 8; r++) s_buf[PAD(512 * r + t)] = a[r];
        __syncthreads();
        {
            int s2 = t >> 6, k = t & 63, base = 512 * s2;
#pragma unroll
            for (int j = 0; j < 8; j++) a[j] = s_buf[PAD(base + k + 64 * j)];
            fwd8(a); twid_fwd(a, s_t512[k]);
            __syncthreads();
#pragma unroll
            for (int r = 0; r < 8; r++) s_buf[PAD(base + 64 * r + k)] = a[r];
            __syncthreads();
        }
        {
            int b3 = t >> 3, k = t & 7, base = 64 * b3;
#pragma unroll
            for (int j = 0; j < 8; j++) a[j] = s_buf[PAD(base + k + 8 * j)];
            fwd8(a); twid_fwd(a, s_t64[k]);
            __syncthreads();
#pragma unroll
            for (int r = 0; r < 8; r++) s_buf[PAD(base + 8 * r + k)] = a[r];
            __syncthreads();
        }
#pragma unroll
        for (int j = 0; j < 8; j++) a[j] = s_buf[PAD(8 * t + j)];
        fwd8(a);
#pragma unroll
        for (int r = 0; r < 8; r++) g_W[8 * t + r] = a[r];
    } else {
        // ---------------- H role ----------------
        float* s_q = (float*)smem_c;   // 2048 floats
        int hb = blk - 69;             // 0..511
        int q = hb >> 7;               // 128 blocks per filter
        int jbase = (hb & 127) << 4;   // 16 j's per block
        FnnW W = (q == 0) ? wf : (q == 1) ? wg : (q == 2) ? wfp : wgp;
        for (int p = tid; p < 2048; p += 512) {
            float x = (q == 0 || q == 2) ? (float)(T - 1 - p) : (float)p;
            float z = W.b2[0];
#pragma unroll
            for (int h = 0; h < 5; h++)
                z += W.w2[h] * tanhf(W.w1[h] * x + W.b1[h]);
            s_q[p] = z * expf(-5.0f * x);
        }
        __syncthreads();
        int warp = tid >> 5, lane = tid & 31;
        int j = jbase + warp;
        long long base = j + (T - 1);
        long long idx0 = (base * (long long)(lane + T - 1)) % NF;
        float s, c;
        sincospif(2.0f * (float)idx0 / (float)NF, &s, &c);
        float2 ph = make_float2(c, -s);
        long long idxs = (base * 32LL) % NF;
        sincospif(2.0f * (float)idxs / (float)NF, &s, &c);
        float2 st = make_float2(c, -s);
        float2 acc = make_float2(0.f, 0.f);
#pragma unroll 8
        for (int it = 0; it < 64; it++) {
            float v = s_q[lane + 32 * it];
            acc.x = fmaf(v, ph.x, acc.x);
            acc.y = fmaf(v, ph.y, acc.y);
            ph = cmul(ph, st);
        }
        for (int off = 16; off; off >>= 1) {
            acc.x += __shfl_down_sync(0xffffffffu, acc.x, off);
            acc.y += __shfl_down_sync(0xffffffffu, acc.y, off);
        }
        if (lane == 0) {
            long long idxU = (2LL * j * M0C + (long long)j * j) % (2LL * NF);
            sincospif((float)idxU / (float)NF, &s, &c);
            g_UH[q * 2048 + j] = cmul(acc, make_float2(c, s));
        }
    }
}

// ================= main kernel (ping-pong buffers) =================
// smem: tw 2048 | Z 2048 | A 4672 | B 4672 | t512 64 | t64 8 | t256 32 | t32 4
#define SMEM_MAIN_F2 (2048 + 2048 + 4672 + 4672 + 64 + 8 + 32 + 4)

__global__ __launch_bounds__(512, 2) void k_main(float* __restrict__ out) {
    float2* s_tw   = smem_c;
    float2* s_Z    = smem_c + 2048;
    float2* sA     = smem_c + 4096;
    float2* sB     = sA + 4672;
    float2* s_t512 = sB + 4672;
    float2* s_t64  = s_t512 + 64;
    float2* s_t256 = s_t64 + 8;
    float2* s_t32  = s_t256 + 32;

    int b = blockIdx.x / 9, c = blockIdx.x % 9;
    int t = threadIdx.x;

    for (int k = t; k < 2048; k += 512) s_tw[k] = g_tw[k];
    if (t < 64) s_t512[t] = g_tw[8 * t];
    if (t < 8)  s_t64[t]  = g_tw[64 * t];
    if (t < 32) s_t256[t] = g_tw[16 * t];
    if (t < 4)  s_t32[t]  = g_tw[128 * t];
    __syncthreads();

    const float* Ar = g_A + (c * BATCH + b) * T;
    const float* Ai = g_B + (c * BATCH + b) * T;

    // ===== phase 0: packed 2048-point FFT (256 active threads, ping-pong) =====
    float2 a[8];
    if (t < 256) {
#pragma unroll
        for (int j = 0; j < 8; j++) {
            int i = t + 256 * j;
            a[j] = make_float2(Ai[i], Ar[i]);   // z = Xir + i*Xr
        }
        fwd8(a); twid_fwd(a, s_tw[2 * t]);
#pragma unroll
        for (int r = 0; r < 8; r++) sA[PAD(256 * r + t)] = a[r];
    }
    __syncthreads();
    if (t < 256) {  // stage2: S=256 q=32  A->B
        int pb = 256 * (t >> 5), pk = t & 31;
#pragma unroll
        for (int j = 0; j < 8; j++) a[j] = sA[PAD(pb + pk + 32 * j)];
        fwd8(a); twid_fwd(a, s_t256[pk]);
#pragma unroll
        for (int r = 0; r < 8; r++) sB[PAD(pb + 32 * r + pk)] = a[r];
    }
    __syncthreads();
    if (t < 256) {  // stage3: S=32 q=4  B->A
        int pb = 32 * (t >> 2), pk = t & 3;
#pragma unroll
        for (int j = 0; j < 8; j++) a[j] = sB[PAD(pb + pk + 4 * j)];
        fwd8(a); twid_fwd(a, s_t32[pk]);
#pragma unroll
        for (int r = 0; r < 8; r++) sA[PAD(pb + 4 * r + pk)] = a[r];
    }
    __syncthreads();
    if (t < 256) {  // stage4: radix-4 x2, unscramble  A->s_Z
#pragma unroll
        for (int h = 0; h < 2; h++) {
            int B = 2 * t + h;
            float2 b4[4];
#pragma unroll
            for (int j = 0; j < 4; j++) b4[j] = sA[PAD(4 * B + j)];
            float2 e0 = cadd(b4[0], b4[2]), e1 = csub(b4[0], b4[2]);
            float2 o0 = cadd(b4[1], b4[3]), o1 = csub(b4[1], b4[3]);
            float2 y0 = cadd(e0, o0), y2 = csub(e0, o0);
            float2 y1 = make_float2(e1.x + o1.y, e1.y - o1.x);
            float2 y3 = make_float2(e1.x - o1.y, e1.y + o1.x);
            int f = (B >> 6) + 8 * ((B >> 3) & 7) + 64 * (B & 7);
            s_Z[f] = y0; s_Z[f + 512] = y1; s_Z[f + 1024] = y2; s_Z[f + 1536] = y3;
        }
    }
    __syncthreads();

    // ===== chirp rounds =====
    float2 c1r[4], Pr[4];
    const float sc = 1.0f / (4096.0f * (float)NF);
    const int k2 = t & 63, base2 = 512 * (t >> 6);
    const int k3 = t & 7,  base3 = 64 * (t >> 3);

    for (int s = 0; s < 4; s++) {
        bool useIr = (s == 0 || s == 2);
        const float2* UH = g_UH + s * 2048;

        // fwd stage1 (half-zero input): s_Z -> A
#pragma unroll
        for (int j = 0; j < 4; j++) {
            int i = t + 512 * j;
            float2 Zj = s_Z[i], Zm = s_Z[(2048 - i) & 2047];
            float2 X = useIr
                ? make_float2(0.5f * (Zj.x + Zm.x), 0.5f * (Zj.y - Zm.y))
                : make_float2(0.5f * (Zj.y + Zm.y), 0.5f * (Zm.x - Zj.x));
            a[j] = cmul(X, UH[i]);
        }
        fwd8h(a); twid_fwd(a, s_tw[t]);
#pragma unroll
        for (int r = 0; r < 8; r++) sA[PAD(512 * r + t)] = a[r];
        __syncthreads();

        // fwd stage2: A -> B
#pragma unroll
        for (int j = 0; j < 8; j++) a[j] = sA[PAD(base2 + k2 + 64 * j)];
        fwd8(a); twid_fwd(a, s_t512[k2]);
#pragma unroll
        for (int r = 0; r < 8; r++) sB[PAD(base2 + 64 * r + k2)] = a[r];
        __syncthreads();

        // fwd stage3: B -> A
#pragma unroll
        for (int j = 0; j < 8; j++) a[j] = sB[PAD(base3 + k3 + 8 * j)];
        fwd8(a); twid_fwd(a, s_t64[k3]);
#pragma unroll
        for (int r = 0; r < 8; r++) sA[PAD(base3 + 8 * r + k3)] = a[r];
        __syncthreads();

        // fwd stage4 + W + inv stage4 (registers): A -> B
#pragma unroll
        for (int j = 0; j < 8; j++) a[j] = sA[PAD(8 * t + j)];
        fwd8(a);
        {
            const float4* W4 = (const float4*)(g_W + 8 * t);
            float4 w = W4[0];
            a[0] = cmul(a[0], make_float2(w.x, w.y)); a[1] = cmul(a[1], make_float2(w.z, w.w));
            w = W4[1];
            a[2] = cmul(a[2], make_float2(w.x, w.y)); a[3] = cmul(a[3], make_float2(w.z, w.w));
            w = W4[2];
            a[4] = cmul(a[4], make_float2(w.x, w.y)); a[5] = cmul(a[5], make_float2(w.z, w.w));
            w = W4[3];
            a[6] = cmul(a[6], make_float2(w.x, w.y)); a[7] = cmul(a[7], make_float2(w.z, w.w));
        }
        inv8(a);
#pragma unroll
        for (int j = 0; j < 8; j++) sB[PAD(8 * t + j)] = a[j];
        __syncthreads();

        // inv stage3: B -> A
#pragma unroll
        for (int r = 0; r < 8; r++) a[r] = sB[PAD(base3 + 8 * r + k3)];
        twid_inv(a, s_t64[k3]); inv8(a);
#pragma unroll
        for (int j = 0; j < 8; j++) sA[PAD(base3 + k3 + 8 * j)] = a[j];
        __syncthreads();

        // inv stage2: A -> B
#pragma unroll
        for (int r = 0; r < 8; r++) a[r] = sA[PAD(base2 + 64 * r + k2)];
        twid_inv(a, s_t512[k2]); inv8(a);
#pragma unroll
        for (int j = 0; j < 8; j++) sB[PAD(base2 + k2 + 64 * j)] = a[j];
        __syncthreads();

        // inv stage1: B -> registers (only m = t + 512j, j<4)
#pragma unroll
        for (int r = 0; r < 8; r++) a[r] = sB[PAD(512 * r + t)];
        twid_inv(a, s_tw[t]); inv8(a);
#pragma unroll
        for (int j = 0; j < 4; j++) {
            float2 v = make_float2(a[j].x * sc, a[j].y * sc);
            if (s == 0) c1r[j] = v;
            else if (s == 1) Pr[j] = cmul(c1r[j], v);
            else if (s == 2) c1r[j] = v;
            else {
                float2 p = cmul(c1r[j], v);
                Pr[j].x += p.x; Pr[j].y += p.y;
            }
        }
        // no sync needed: next stage1 writes A; all A-readers finished before last sync
    }

#pragma unroll
    for (int j = 0; j < 4; j++) {
        int m = t + 512 * j;
        float2 psi = g_psi[m];
        out[(b * T + m) * 9 + c] = Pr[j].x * psi.x - Pr[j].y * psi.y;
    }
}

// ---------------- launch ----------------
extern "C" void kernel_launch(void* const* d_in, const int* in_sizes, int n_in,
                              void* d_out, int out_size) {
    const float* xd = (const float*)d_in[0];
    const float* A1 = (const float*)d_in[1];
    const float* A2 = (const float*)d_in[2];
    FnnW wf  = {(const float*)d_in[3],  (const float*)d_in[4],  (const float*)d_in[5],  (const float*)d_in[6]};
    FnnW wg  = {(const float*)d_in[7],  (const float*)d_in[8],  (const float*)d_in[9],  (const float*)d_in[10]};
    FnnW wfp = {(const float*)d_in[11], (const float*)d_in[12], (const float*)d_in[13], (const float*)d_in[14]};
    FnnW wgp = {(const float*)d_in[15], (const float*)d_in[16], (const float*)d_in[17], (const float*)d_in[18]};
    float* out = (float*)d_out;

    int smem_pre  = (2048 + 4672 + 64 + 8) * sizeof(float2);   // 54,336 B
    int smem_main = SMEM_MAIN_F2 * sizeof(float2);             // 108,384 B
    cudaFuncSetAttribute(k_pre,  cudaFuncAttributeMaxDynamicSharedMemorySize, smem_pre);
    cudaFuncSetAttribute(k_main, cudaFuncAttributeMaxDynamicSharedMemorySize, smem_main);

    k_pre<<<581, 512, smem_pre>>>(xd, A1, A2, wf, wg, wfp, wgp);
    k_main<<<BATCH * 9, 512, smem_main>>>(out);
}